// round 13
// baseline (speedup 1.0000x reference)
#include <cuda_runtime.h>
#include <cuda_pipeline.h>
#include <math.h>
#include <stdint.h>

#define BB 256
#define UU 4096
#define VV 80
#define HH 1024
#define KK 10
#define NT 1024         // threads per block = 2 halves of 512
#define HT 512          // threads per half (one batch row each)
#define NGRP 6          // einsum u-groups (NGRP*VV = 480 <= HT)
#define UCAP 48         // prefetched c rows per b (covers typical ucut; fallback beyond)
#define ZSTART 64       // bulk zeros cover [ZSTART, UU]; phi phase covers [0, ZSTART)

// Output layout (concatenated flattened, reference return order):
//   w               : BB*VV      floats (offset 0)
//   new_kappa       : BB*KK      floats (offset BB*VV)
//   phi_termination : BB*(UU+1)  floats (offset BB*VV + BB*KK)

#define HSYNC() asm volatile("bar.sync %0, %1;" :: "r"(s + 1), "r"(HT) : "memory")

__global__ __launch_bounds__(NT, 1) void softwindow_kernel(
    const float* __restrict__ x,        // [BB,1,HH]
    const float* __restrict__ c,        // [BB,UU,VV]
    const float* __restrict__ kappa,    // [BB,KK]
    const float* __restrict__ W,        // [3*KK,HH]
    const float* __restrict__ bias,     // [3*KK]
    const int*   __restrict__ lens32,   // [BB] int32 OR int64 viewed as int32 pairs
    float* __restrict__ out)
{
    __shared__ float c_sh[2][UCAP * VV];     // 30 KB
    __shared__ float phi_sh[2][UCAP];
    __shared__ float alpha_sh[2][KK];
    __shared__ float beta_sh[2][KK];
    __shared__ float nk_sh[2][KK];
    __shared__ float part_sh[2][NGRP][VV];   // 3.84 KB
    __shared__ int   or_sh[2][4];

    const int tid_g = threadIdx.x;
    const int s     = tid_g >> 9;        // half id: 0 or 1
    const int tid   = tid_g & (HT - 1);  // local tid within half
    const int b     = 2 * blockIdx.x + s;
    const int warp  = tid >> 5;
    const int lane  = tid & 31;

    float* phit = out + (size_t)BB * VV + (size_t)BB * KK + (size_t)b * (UU + 1);

    // ---- hoisted scalar loads (addresses data-independent; issue at entry) ----
    // warps 4..13 own j1 = warp+16 in [20,30) -> new_kappa index warp-4
    float kap_r = 0.f;
    if (lane == 0 && warp >= 4 && warp < 14) kap_r = kappa[(size_t)b * KK + (warp - 4)];
    const int len32_r = lens32[b];        // candidate if dtype == int32
    const int len64_r = lens32[2 * b];    // candidate if dtype == int64 (low word)

    // ---- dtype probe: int64 layout <=> all odd int32 words in [0,256) are zero ----
    if (tid < 128) {
        int v = lens32[2 * tid + 1];
        #pragma unroll
        for (int o = 16; o; o >>= 1) v |= __shfl_xor_sync(0xffffffffu, v, o);
        if (lane == 0) or_sh[s][warp] = v;
    }

    // ---- PHASE 1: lin = x[b] @ W^T + bias, 2 dots/warp, then lane0 directly
    //      computes & stores its own alpha/beta/new_kappa (no warp-0 phase) ----
    {
        const float4* xs = (const float4*)(x + (size_t)b * HH);
        const int j0 = warp;
        const int j1 = warp + 16;
        const bool h1 = (j1 < 3 * KK);                 // warps 14,15 have no j1
        const float4* W0 = (const float4*)(W + (size_t)j0 * HH);
        const float4* W1 = (const float4*)(W + (size_t)(h1 ? j1 : j0) * HH);
        float s0 = 0.f, s1 = 0.f, s2 = 0.f, s3 = 0.f;
        float t0 = 0.f, t1 = 0.f, t2 = 0.f, t3 = 0.f;
        #pragma unroll
        for (int i = 0; i < HH / 4 / 32; i++) {        // 8 iterations, MLP ~24
            float4 xv = xs[i * 32 + lane];
            float4 w0 = W0[i * 32 + lane];
            float4 w1 = W1[i * 32 + lane];
            s0 = fmaf(xv.x, w0.x, s0);  t0 = fmaf(xv.x, w1.x, t0);
            s1 = fmaf(xv.y, w0.y, s1);  t1 = fmaf(xv.y, w1.y, t1);
            s2 = fmaf(xv.z, w0.z, s2);  t2 = fmaf(xv.z, w1.z, t2);
            s3 = fmaf(xv.w, w0.w, s3);  t3 = fmaf(xv.w, w1.w, t3);
        }
        float sv = (s0 + s1) + (s2 + s3);
        float tv = (t0 + t1) + (t2 + t3);
        #pragma unroll
        for (int o = 16; o; o >>= 1) {
            sv += __shfl_xor_sync(0xffffffffu, sv, o);
            tv += __shfl_xor_sync(0xffffffffu, tv, o);
        }
        if (lane == 0) {
            float va = sv + bias[j0];
            if (j0 < KK)            alpha_sh[s][j0]      = __expf(va);
            else                    beta_sh[s][j0 - KK]  = __expf(va);   // j0 in 10..15
            if (h1) {
                float vb = tv + bias[j1];
                if (j1 < 2 * KK) {
                    beta_sh[s][j1 - KK] = __expf(vb);                    // j1 in 16..19
                } else {
                    float nk = kap_r + __expf(vb - 3.9f);                // j1 in 20..29
                    nk_sh[s][j1 - 2 * KK] = nk;
                    out[(size_t)BB * VV + (size_t)b * KK + (j1 - 2 * KK)] = nk;
                }
            }
        }
    }

    // ---- PHASE 2 (fire-and-forget): prefetch first UCAP rows of c[b] (15 KB) ----
    {
        const float4* src = (const float4*)(c + (size_t)b * UU * VV);
        float4*       dst = (float4*)c_sh[s];
        for (int i = tid; i < UCAP * VV / 4; i += HT)
            __pipeline_memcpy_async(&dst[i], &src[i], 16);
        __pipeline_commit();
    }

    // ---- PHASE 3 (fire-and-forget stores): zeros for phi_termination[ZSTART..UU].
    //      phi overwrites [ZSTART, ucut] later if needed; named barriers order it. ----
    {
        int start = ZSTART;
        int mis = (int)((16u - ((uint32_t)(uintptr_t)(phit + start) & 15u)) & 15u) >> 2;
        if (tid < mis) phit[start + tid] = 0.f;
        start += mis;
        const int nv = (UU + 1 - start) >> 2;
        float4* p4 = (float4*)(phit + start);
        const float4 z = make_float4(0.f, 0.f, 0.f, 0.f);
        for (int i = tid; i < nv; i += HT) p4[i] = z;
        const int rem = start + nv * 4;
        if (tid < (UU + 1 - rem)) phit[rem + tid] = 0.f;
    }
    HSYNC();   // barrier 1: params + zeros + probe visible

    // ---- every warp redundantly computes the cutoff (no extra barrier):
    //      beyond nk + sqrt(105/beta), fp32 exp arg < -105 => exp == 0 exactly ----
    int ucut;
    {
        float cut = 0.f;
        if (lane < KK)
            cut = nk_sh[s][lane] + sqrtf(105.0f / beta_sh[s][lane]);
        #pragma unroll
        for (int o = 16; o; o >>= 1)
            cut = fmaxf(cut, __shfl_xor_sync(0xffffffffu, cut, o));
        int uc = (int)cut + 1;
        if (uc > UU) uc = UU;       // cap: correctness never depends on the cutoff
        if (uc < 0)  uc = 0;
        ucut = uc;
    }

    // ---- phi phase covers [0, max(ucut, ZSTART-1)]: computed vals for u <= ucut,
    //      literal zeros for (ucut, ZSTART) ----
    {
        const int utop = (ucut > ZSTART - 1) ? ucut : (ZSTART - 1);
        if (tid <= utop) {
            float a_r[KK], be_r[KK], nk_r[KK];
            #pragma unroll
            for (int k = 0; k < KK; k++) {
                a_r[k] = alpha_sh[s][k]; be_r[k] = beta_sh[s][k]; nk_r[k] = nk_sh[s][k];
            }
            for (int u = tid; u <= utop; u += HT) {
                float val = 0.f;
                if (u <= ucut) {
                    const float uf = (float)u;
                    #pragma unroll
                    for (int k = 0; k < KK; k++) {
                        float d   = nk_r[k] - uf;
                        float arg = -be_r[k] * d * d;
                        val += a_r[k] * __expf(arg);   // fast exp: ~1e-6 rel, << 1e-3
                    }
                }
                phit[u] = val;
                if (u < UCAP) phi_sh[s][u] = val;
            }
        }
    }
    __pipeline_wait_prior(0);   // c prefetch done (latency long since hidden)
    HSYNC();   // barrier 2: phi visible

    // ---- einsum: w[b,v] = sum_u phi[u]*c[b,u,v], u-parallel over NGRP groups ----
    const int orv = or_sh[s][0] | or_sh[s][1] | or_sh[s][2] | or_sh[s][3];
    const int len = (orv == 0) ? len64_r : len32_r;
    int umax = ucut + 1;
    if (len < umax) umax = len;
    if (umax < 0)   umax = 0;
    if (umax > UU)  umax = UU;

    if (tid < NGRP * VV) {
        const int v = tid % VV;
        const int g = tid / VV;
        float acc = 0.f;
        int ufast = umax < UCAP ? umax : UCAP;
        for (int u = g; u < ufast; u += NGRP)
            acc = fmaf(phi_sh[s][u], c_sh[s][u * VV + v], acc);
        if (umax > UCAP) {
            // rare fallback: gmem c + recomputed phi
            int u0 = g;
            while (u0 < UCAP) u0 += NGRP;
            const float* cb = c + (size_t)b * UU * VV + v;
            for (int u = u0; u < umax; u += NGRP) {
                const float uf = (float)u;
                float ph = 0.f;
                #pragma unroll
                for (int k = 0; k < KK; k++) {
                    float d = nk_sh[s][k] - uf;
                    ph += alpha_sh[s][k] * __expf(-beta_sh[s][k] * d * d);
                }
                acc = fmaf(ph, cb[(size_t)u * VV], acc);
            }
        }
        part_sh[s][g][v] = acc;
    }
    HSYNC();   // barrier 3: partials visible
    if (tid < VV) {
        float acc = 0.f;
        #pragma unroll
        for (int g = 0; g < NGRP; g++) acc += part_sh[s][g][tid];
        out[(size_t)b * VV + tid] = acc;
    }
}

extern "C" void kernel_launch(void* const* d_in, const int* in_sizes, int n_in,
                              void* d_out, int out_size) {
    const float* x     = (const float*)d_in[0];
    const float* c     = (const float*)d_in[1];
    const float* kappa = (const float*)d_in[2];
    const float* W     = (const float*)d_in[3];
    const float* bias  = (const float*)d_in[4];
    const int*   lens  = (const int*)d_in[5];
    float* out = (float*)d_out;

    softwindow_kernel<<<BB / 2, NT>>>(x, c, kappa, W, bias, lens, out);
}

// round 14
// speedup vs baseline: 1.0031x; 1.0031x over previous
#include <cuda_runtime.h>
#include <cuda_pipeline.h>
#include <math.h>
#include <stdint.h>

#define BB 256
#define UU 4096
#define VV 80
#define HH 1024
#define KK 10
#define NT 1024         // threads per block = 2 halves of 512
#define HT 512          // threads per half (one batch row each)
#define UCAP 48         // prefetched c rows per b (covers typical ucut; fallback beyond)
#define ZSTART 64       // bulk zeros cover [ZSTART, UU]; phi phase covers [0, ZSTART)

// Output layout (concatenated flattened, reference return order):
//   w               : BB*VV      floats (offset 0)
//   new_kappa       : BB*KK      floats (offset BB*VV)
//   phi_termination : BB*(UU+1)  floats (offset BB*VV + BB*KK)

#define HSYNC() asm volatile("bar.sync %0, %1;" :: "r"(s + 1), "r"(HT) : "memory")

__global__ __launch_bounds__(NT, 1) void softwindow_kernel(
    const float* __restrict__ x,        // [BB,1,HH]
    const float* __restrict__ c,        // [BB,UU,VV]
    const float* __restrict__ kappa,    // [BB,KK]
    const float* __restrict__ W,        // [3*KK,HH]
    const float* __restrict__ bias,     // [3*KK]
    const int*   __restrict__ lens32,   // [BB] int32 OR int64 viewed as int32 pairs
    float* __restrict__ out)
{
    __shared__ float c_sh[2][UCAP * VV];     // 30 KB
    __shared__ float phi_sh[2][UCAP];
    __shared__ float alpha_sh[2][KK];
    __shared__ float beta_sh[2][KK];
    __shared__ float nk_sh[2][KK];
    __shared__ int   or_sh[2][4];

    const int tid_g = threadIdx.x;
    const int s     = tid_g >> 9;        // half id: 0 or 1
    const int tid   = tid_g & (HT - 1);  // local tid within half
    const int b     = 2 * blockIdx.x + s;
    const int warp  = tid >> 5;
    const int lane  = tid & 31;

    float* phit = out + (size_t)BB * VV + (size_t)BB * KK + (size_t)b * (UU + 1);

    // ---- hoisted scalar loads (addresses data-independent; issue at entry) ----
    // warps 4..13 own j1 = warp+16 in [20,30) -> new_kappa index warp-4
    float kap_r = 0.f;
    if (lane == 0 && warp >= 4 && warp < 14) kap_r = kappa[(size_t)b * KK + (warp - 4)];
    const int len32_r = lens32[b];        // candidate if dtype == int32
    const int len64_r = lens32[2 * b];    // candidate if dtype == int64 (low word)

    // ---- dtype probe: int64 layout <=> all odd int32 words in [0,256) are zero ----
    if (tid < 128) {
        int v = lens32[2 * tid + 1];
        #pragma unroll
        for (int o = 16; o; o >>= 1) v |= __shfl_xor_sync(0xffffffffu, v, o);
        if (lane == 0) or_sh[s][warp] = v;
    }

    // ---- PHASE 1: lin = x[b] @ W^T + bias, 2 dots/warp, then lane0 directly
    //      computes & stores its own alpha/beta/new_kappa (no warp-0 phase) ----
    {
        const float4* xs = (const float4*)(x + (size_t)b * HH);
        const int j0 = warp;
        const int j1 = warp + 16;
        const bool h1 = (j1 < 3 * KK);                 // warps 14,15 have no j1
        const float4* W0 = (const float4*)(W + (size_t)j0 * HH);
        const float4* W1 = (const float4*)(W + (size_t)(h1 ? j1 : j0) * HH);
        float s0 = 0.f, s1 = 0.f, s2 = 0.f, s3 = 0.f;
        float t0 = 0.f, t1 = 0.f, t2 = 0.f, t3 = 0.f;
        #pragma unroll
        for (int i = 0; i < HH / 4 / 32; i++) {        // 8 iterations, MLP ~24
            float4 xv = xs[i * 32 + lane];
            float4 w0 = W0[i * 32 + lane];
            float4 w1 = W1[i * 32 + lane];
            s0 = fmaf(xv.x, w0.x, s0);  t0 = fmaf(xv.x, w1.x, t0);
            s1 = fmaf(xv.y, w0.y, s1);  t1 = fmaf(xv.y, w1.y, t1);
            s2 = fmaf(xv.z, w0.z, s2);  t2 = fmaf(xv.z, w1.z, t2);
            s3 = fmaf(xv.w, w0.w, s3);  t3 = fmaf(xv.w, w1.w, t3);
        }
        float sv = (s0 + s1) + (s2 + s3);
        float tv = (t0 + t1) + (t2 + t3);
        #pragma unroll
        for (int o = 16; o; o >>= 1) {
            sv += __shfl_xor_sync(0xffffffffu, sv, o);
            tv += __shfl_xor_sync(0xffffffffu, tv, o);
        }
        if (lane == 0) {
            float va = sv + bias[j0];
            if (j0 < KK)            alpha_sh[s][j0]      = __expf(va);
            else                    beta_sh[s][j0 - KK]  = __expf(va);   // j0 in 10..15
            if (h1) {
                float vb = tv + bias[j1];
                if (j1 < 2 * KK) {
                    beta_sh[s][j1 - KK] = __expf(vb);                    // j1 in 16..19
                } else {
                    float nk = kap_r + __expf(vb - 3.9f);                // j1 in 20..29
                    nk_sh[s][j1 - 2 * KK] = nk;
                    out[(size_t)BB * VV + (size_t)b * KK + (j1 - 2 * KK)] = nk;
                }
            }
        }
    }

    // ---- PHASE 2 (fire-and-forget): prefetch first UCAP rows of c[b] (15 KB) ----
    {
        const float4* src = (const float4*)(c + (size_t)b * UU * VV);
        float4*       dst = (float4*)c_sh[s];
        for (int i = tid; i < UCAP * VV / 4; i += HT)
            __pipeline_memcpy_async(&dst[i], &src[i], 16);
        __pipeline_commit();
    }

    // ---- PHASE 3 (fire-and-forget stores): zeros for phi_termination[ZSTART..UU].
    //      phi overwrites [ZSTART, ucut] later if needed; named barriers order it. ----
    {
        int start = ZSTART;
        int mis = (int)((16u - ((uint32_t)(uintptr_t)(phit + start) & 15u)) & 15u) >> 2;
        if (tid < mis) phit[start + tid] = 0.f;
        start += mis;
        const int nv = (UU + 1 - start) >> 2;
        float4* p4 = (float4*)(phit + start);
        const float4 z = make_float4(0.f, 0.f, 0.f, 0.f);
        for (int i = tid; i < nv; i += HT) p4[i] = z;
        const int rem = start + nv * 4;
        if (tid < (UU + 1 - rem)) phit[rem + tid] = 0.f;
    }
    HSYNC();   // barrier 1: params + zeros + probe visible

    // ---- every warp redundantly computes the cutoff (no extra barrier):
    //      beyond nk + sqrt(105/beta), fp32 exp arg < -105 => exp == 0 exactly ----
    int ucut;
    {
        float cut = 0.f;
        if (lane < KK)
            cut = nk_sh[s][lane] + sqrtf(105.0f / beta_sh[s][lane]);
        #pragma unroll
        for (int o = 16; o; o >>= 1)
            cut = fmaxf(cut, __shfl_xor_sync(0xffffffffu, cut, o));
        int uc = (int)cut + 1;
        if (uc > UU) uc = UU;       // cap: correctness never depends on the cutoff
        if (uc < 0)  uc = 0;
        ucut = uc;
    }

    // ---- len / umax (off the post-phi path; or_sh valid after barrier 1) ----
    const int orv = or_sh[s][0] | or_sh[s][1] | or_sh[s][2] | or_sh[s][3];
    const int len = (orv == 0) ? len64_r : len32_r;
    int umax = ucut + 1;
    if (len < umax) umax = len;
    if (umax < 0)   umax = 0;
    if (umax > UU)  umax = UU;

    // ---- phi phase covers [0, max(ucut, ZSTART-1)]: computed vals for u <= ucut,
    //      literal zeros for (ucut, ZSTART) ----
    {
        const int utop = (ucut > ZSTART - 1) ? ucut : (ZSTART - 1);
        if (tid <= utop) {
            float a_r[KK], be_r[KK], nk_r[KK];
            #pragma unroll
            for (int k = 0; k < KK; k++) {
                a_r[k] = alpha_sh[s][k]; be_r[k] = beta_sh[s][k]; nk_r[k] = nk_sh[s][k];
            }
            for (int u = tid; u <= utop; u += HT) {
                float val = 0.f;
                if (u <= ucut) {
                    const float uf = (float)u;
                    #pragma unroll
                    for (int k = 0; k < KK; k++) {
                        float d   = nk_r[k] - uf;
                        float arg = -be_r[k] * d * d;
                        val += a_r[k] * __expf(arg);   // fast exp: ~1e-6 rel, << 1e-3
                    }
                }
                phit[u] = val;
                if (u < UCAP) phi_sh[s][u] = val;
            }
        }
    }
    __pipeline_wait_prior(0);   // c prefetch done (latency long since hidden)
    HSYNC();   // barrier 2: phi visible — LAST barrier; warps 3..15 exit after this

    // ---- einsum: w[b,v] = sum_u phi[u]*c[b,u,v]; 80 threads, dual accumulators.
    //      No partial smem, no extra barrier, no reduce phase. ----
    if (tid < VV) {
        const int v = tid;
        float acc0 = 0.f, acc1 = 0.f;
        const int ufast = umax < UCAP ? umax : UCAP;
        int u = 0;
        for (; u + 1 < ufast; u += 2) {
            acc0 = fmaf(phi_sh[s][u],     c_sh[s][u * VV + v],       acc0);
            acc1 = fmaf(phi_sh[s][u + 1], c_sh[s][(u + 1) * VV + v], acc1);
        }
        if (u < ufast)
            acc0 = fmaf(phi_sh[s][u], c_sh[s][u * VV + v], acc0);
        if (umax > UCAP) {
            // rare fallback: gmem c + recomputed phi
            const float* cb = c + (size_t)b * UU * VV + v;
            for (int uu = UCAP; uu < umax; uu++) {
                const float uf = (float)uu;
                float ph = 0.f;
                #pragma unroll
                for (int k = 0; k < KK; k++) {
                    float d = nk_sh[s][k] - uf;
                    ph += alpha_sh[s][k] * __expf(-beta_sh[s][k] * d * d);
                }
                acc0 = fmaf(ph, cb[(size_t)uu * VV], acc0);
            }
        }
        out[(size_t)b * VV + v] = acc0 + acc1;
    }
}

extern "C" void kernel_launch(void* const* d_in, const int* in_sizes, int n_in,
                              void* d_out, int out_size) {
    const float* x     = (const float*)d_in[0];
    const float* c     = (const float*)d_in[1];
    const float* kappa = (const float*)d_in[2];
    const float* W     = (const float*)d_in[3];
    const float* bias  = (const float*)d_in[4];
    const int*   lens  = (const int*)d_in[5];
    float* out = (float*)d_out;

    softwindow_kernel<<<BB / 2, NT>>>(x, c, kappa, W, bias, lens, out);
}

// round 15
// speedup vs baseline: 1.1038x; 1.1003x over previous
#include <cuda_runtime.h>
#include <cuda_pipeline.h>
#include <math.h>
#include <stdint.h>

#define BB 256
#define UU 4096
#define VV 80
#define HH 1024
#define KK 10
#define NT 1024         // threads per block = 2 halves of 512
#define HT 512          // threads per half (one batch row each)
#define NGRP 6          // einsum u-groups (NGRP*VV = 480 <= HT)
#define UCAP 48         // prefetched c rows per b (covers typical ucut; fallback beyond)
#define ZSTART 64       // bulk zeros cover [ZSTART, UU]; phi phase covers [0, ZSTART)

// Output layout (concatenated flattened, reference return order):
//   w               : BB*VV      floats (offset 0)
//   new_kappa       : BB*KK      floats (offset BB*VV)
//   phi_termination : BB*(UU+1)  floats (offset BB*VV + BB*KK)

#define HSYNC() asm volatile("bar.sync %0, %1;" :: "r"(s + 1), "r"(HT) : "memory")

__global__ __launch_bounds__(NT, 1) void softwindow_kernel(
    const float* __restrict__ x,        // [BB,1,HH]
    const float* __restrict__ c,        // [BB,UU,VV]
    const float* __restrict__ kappa,    // [BB,KK]
    const float* __restrict__ W,        // [3*KK,HH]
    const float* __restrict__ bias,     // [3*KK]
    const int*   __restrict__ lens32,   // [BB] int32 OR int64 viewed as int32 pairs
    float* __restrict__ out)
{
    __shared__ float c_sh[2][UCAP * VV];     // 30 KB
    __shared__ float phi_sh[2][UCAP];
    __shared__ float alpha_sh[2][KK];
    __shared__ float beta_sh[2][KK];
    __shared__ float nk_sh[2][KK];
    __shared__ float part_sh[2][NGRP][VV];   // 3.84 KB
    __shared__ int   or_sh[2][4];

    const int tid_g = threadIdx.x;
    const int s     = tid_g >> 9;        // half id: 0 or 1
    const int tid   = tid_g & (HT - 1);  // local tid within half
    const int b     = 2 * blockIdx.x + s;
    const int warp  = tid >> 5;
    const int lane  = tid & 31;

    float* phit = out + (size_t)BB * VV + (size_t)BB * KK + (size_t)b * (UU + 1);

    // ---- hoisted scalar loads (addresses data-independent; issue at entry) ----
    // warps 4..13 own j1 = warp+16 in [20,30) -> new_kappa index warp-4
    float kap_r = 0.f;
    if (lane == 0 && warp >= 4 && warp < 14) kap_r = kappa[(size_t)b * KK + (warp - 4)];
    const int len32_r = lens32[b];        // candidate if dtype == int32
    const int len64_r = lens32[2 * b];    // candidate if dtype == int64 (low word)

    // ---- dtype probe: int64 layout <=> all odd int32 words in [0,256) are zero ----
    if (tid < 128) {
        int v = lens32[2 * tid + 1];
        #pragma unroll
        for (int o = 16; o; o >>= 1) v |= __shfl_xor_sync(0xffffffffu, v, o);
        if (lane == 0) or_sh[s][warp] = v;
    }

    // ---- PHASE 1: lin = x[b] @ W^T + bias, 2 dots/warp, then lane0 directly
    //      computes & stores its own alpha/beta/new_kappa (no warp-0 phase) ----
    {
        const float4* xs = (const float4*)(x + (size_t)b * HH);
        const int j0 = warp;
        const int j1 = warp + 16;
        const bool h1 = (j1 < 3 * KK);                 // warps 14,15 have no j1
        const float4* W0 = (const float4*)(W + (size_t)j0 * HH);
        const float4* W1 = (const float4*)(W + (size_t)(h1 ? j1 : j0) * HH);
        float s0 = 0.f, s1 = 0.f, s2 = 0.f, s3 = 0.f;
        float t0 = 0.f, t1 = 0.f, t2 = 0.f, t3 = 0.f;
        #pragma unroll
        for (int i = 0; i < HH / 4 / 32; i++) {        // 8 iterations, MLP ~24
            float4 xv = xs[i * 32 + lane];
            float4 w0 = W0[i * 32 + lane];
            float4 w1 = W1[i * 32 + lane];
            s0 = fmaf(xv.x, w0.x, s0);  t0 = fmaf(xv.x, w1.x, t0);
            s1 = fmaf(xv.y, w0.y, s1);  t1 = fmaf(xv.y, w1.y, t1);
            s2 = fmaf(xv.z, w0.z, s2);  t2 = fmaf(xv.z, w1.z, t2);
            s3 = fmaf(xv.w, w0.w, s3);  t3 = fmaf(xv.w, w1.w, t3);
        }
        float sv = (s0 + s1) + (s2 + s3);
        float tv = (t0 + t1) + (t2 + t3);
        #pragma unroll
        for (int o = 16; o; o >>= 1) {
            sv += __shfl_xor_sync(0xffffffffu, sv, o);
            tv += __shfl_xor_sync(0xffffffffu, tv, o);
        }
        if (lane == 0) {
            float va = sv + bias[j0];
            if (j0 < KK)            alpha_sh[s][j0]      = __expf(va);
            else                    beta_sh[s][j0 - KK]  = __expf(va);   // j0 in 10..15
            if (h1) {
                float vb = tv + bias[j1];
                if (j1 < 2 * KK) {
                    beta_sh[s][j1 - KK] = __expf(vb);                    // j1 in 16..19
                } else {
                    float nk = kap_r + __expf(vb - 3.9f);                // j1 in 20..29
                    nk_sh[s][j1 - 2 * KK] = nk;
                    out[(size_t)BB * VV + (size_t)b * KK + (j1 - 2 * KK)] = nk;
                }
            }
        }
    }

    // ---- PHASE 2 (fire-and-forget): prefetch first UCAP rows of c[b] (15 KB) ----
    {
        const float4* src = (const float4*)(c + (size_t)b * UU * VV);
        float4*       dst = (float4*)c_sh[s];
        for (int i = tid; i < UCAP * VV / 4; i += HT)
            __pipeline_memcpy_async(&dst[i], &src[i], 16);
        __pipeline_commit();
    }

    // ---- PHASE 3 (fire-and-forget stores): zeros for phi_termination[ZSTART..UU].
    //      phi overwrites [ZSTART, ucut] later if needed; named barriers order it. ----
    {
        int start = ZSTART;
        int mis = (int)((16u - ((uint32_t)(uintptr_t)(phit + start) & 15u)) & 15u) >> 2;
        if (tid < mis) phit[start + tid] = 0.f;
        start += mis;
        const int nv = (UU + 1 - start) >> 2;
        float4* p4 = (float4*)(phit + start);
        const float4 z = make_float4(0.f, 0.f, 0.f, 0.f);
        for (int i = tid; i < nv; i += HT) p4[i] = z;
        const int rem = start + nv * 4;
        if (tid < (UU + 1 - rem)) phit[rem + tid] = 0.f;
    }
    HSYNC();   // barrier 1: params + zeros + probe visible

    // ---- every warp redundantly computes the cutoff (no extra barrier):
    //      beyond nk + sqrt(105/beta), fp32 exp arg < -105 => exp == 0 exactly ----
    int ucut;
    {
        float cut = 0.f;
        if (lane < KK)
            cut = nk_sh[s][lane] + sqrtf(105.0f / beta_sh[s][lane]);
        #pragma unroll
        for (int o = 16; o; o >>= 1)
            cut = fmaxf(cut, __shfl_xor_sync(0xffffffffu, cut, o));
        int uc = (int)cut + 1;
        if (uc > UU) uc = UU;       // cap: correctness never depends on the cutoff
        if (uc < 0)  uc = 0;
        ucut = uc;
    }

    // ---- len / umax (off the post-phi path; or_sh valid after barrier 1) ----
    const int orv = or_sh[s][0] | or_sh[s][1] | or_sh[s][2] | or_sh[s][3];
    const int len = (orv == 0) ? len64_r : len32_r;
    int umax = ucut + 1;
    if (len < umax) umax = len;
    if (umax < 0)   umax = 0;
    if (umax > UU)  umax = UU;

    // ---- phi phase covers [0, max(ucut, ZSTART-1)]: computed vals for u <= ucut,
    //      literal zeros for (ucut, ZSTART) ----
    {
        const int utop = (ucut > ZSTART - 1) ? ucut : (ZSTART - 1);
        if (tid <= utop) {
            float a_r[KK], be_r[KK], nk_r[KK];
            #pragma unroll
            for (int k = 0; k < KK; k++) {
                a_r[k] = alpha_sh[s][k]; be_r[k] = beta_sh[s][k]; nk_r[k] = nk_sh[s][k];
            }
            for (int u = tid; u <= utop; u += HT) {
                float val = 0.f;
                if (u <= ucut) {
                    const float uf = (float)u;
                    #pragma unroll
                    for (int k = 0; k < KK; k++) {
                        float d   = nk_r[k] - uf;
                        float arg = -be_r[k] * d * d;
                        val += a_r[k] * __expf(arg);   // fast exp: ~1e-6 rel, << 1e-3
                    }
                }
                phit[u] = val;
                if (u < UCAP) phi_sh[s][u] = val;
            }
        }
    }
    __pipeline_wait_prior(0);   // c prefetch done (latency long since hidden)
    HSYNC();   // barrier 2: phi visible

    // ---- einsum: w[b,v] = sum_u phi[u]*c[b,u,v], u-parallel over NGRP groups ----
    if (tid < NGRP * VV) {
        const int v = tid % VV;
        const int g = tid / VV;
        float acc = 0.f;
        int ufast = umax < UCAP ? umax : UCAP;
        for (int u = g; u < ufast; u += NGRP)
            acc = fmaf(phi_sh[s][u], c_sh[s][u * VV + v], acc);
        if (umax > UCAP) {
            // rare fallback: gmem c + recomputed phi
            int u0 = g;
            while (u0 < UCAP) u0 += NGRP;
            const float* cb = c + (size_t)b * UU * VV + v;
            for (int u = u0; u < umax; u += NGRP) {
                const float uf = (float)u;
                float ph = 0.f;
                #pragma unroll
                for (int k = 0; k < KK; k++) {
                    float d = nk_sh[s][k] - uf;
                    ph += alpha_sh[s][k] * __expf(-beta_sh[s][k] * d * d);
                }
                acc = fmaf(ph, cb[(size_t)u * VV], acc);
            }
        }
        part_sh[s][g][v] = acc;
    }
    HSYNC();   // barrier 3: partials visible
    if (tid < VV) {
        float acc = 0.f;
        #pragma unroll
        for (int g = 0; g < NGRP; g++) acc += part_sh[s][g][tid];
        out[(size_t)b * VV + tid] = acc;
    }
}

extern "C" void kernel_launch(void* const* d_in, const int* in_sizes, int n_in,
                              void* d_out, int out_size) {
    const float* x     = (const float*)d_in[0];
    const float* c     = (const float*)d_in[1];
    const float* kappa = (const float*)d_in[2];
    const float* W     = (const float*)d_in[3];
    const float* bias  = (const float*)d_in[4];
    const int*   lens  = (const int*)d_in[5];
    float* out = (float*)d_out;

    softwindow_kernel<<<BB / 2, NT>>>(x, c, kappa, W, bias, lens, out);
}

// round 16
// speedup vs baseline: 1.1076x; 1.0035x over previous
#include <cuda_runtime.h>
#include <cuda_pipeline.h>
#include <math.h>
#include <stdint.h>

#define BB 256
#define UU 4096
#define VV 80
#define HH 1024
#define KK 10
#define NT 1024         // threads per block = 2 halves of 512
#define HT 512          // threads per half (one batch row each)
#define NGRP 4          // einsum u-groups; 4 partials per v live in one warp
#define UCAP 48         // prefetched c rows per b (covers typical ucut; fallback beyond)
#define ZSTART 64       // bulk zeros cover [ZSTART, UU]; phi phase covers [0, ZSTART)

// Output layout (concatenated flattened, reference return order):
//   w               : BB*VV      floats (offset 0)
//   new_kappa       : BB*KK      floats (offset BB*VV)
//   phi_termination : BB*(UU+1)  floats (offset BB*VV + BB*KK)

#define HSYNC() asm volatile("bar.sync %0, %1;" :: "r"(s + 1), "r"(HT) : "memory")

__global__ __launch_bounds__(NT, 1) void softwindow_kernel(
    const float* __restrict__ x,        // [BB,1,HH]
    const float* __restrict__ c,        // [BB,UU,VV]
    const float* __restrict__ kappa,    // [BB,KK]
    const float* __restrict__ W,        // [3*KK,HH]
    const float* __restrict__ bias,     // [3*KK]
    const int*   __restrict__ lens32,   // [BB] int32 OR int64 viewed as int32 pairs
    float* __restrict__ out)
{
    __shared__ float c_sh[2][UCAP * VV];     // 30 KB
    __shared__ float phi_sh[2][UCAP];
    __shared__ float alpha_sh[2][KK];
    __shared__ float beta_sh[2][KK];
    __shared__ float nk_sh[2][KK];
    __shared__ int   or_sh[2][4];

    const int tid_g = threadIdx.x;
    const int s     = tid_g >> 9;        // half id: 0 or 1
    const int tid   = tid_g & (HT - 1);  // local tid within half
    const int b     = 2 * blockIdx.x + s;
    const int warp  = tid >> 5;
    const int lane  = tid & 31;

    float* phit = out + (size_t)BB * VV + (size_t)BB * KK + (size_t)b * (UU + 1);

    // ---- hoisted scalar loads (addresses data-independent; issue at entry) ----
    // warps 4..13 own j1 = warp+16 in [20,30) -> new_kappa index warp-4
    float kap_r = 0.f;
    if (lane == 0 && warp >= 4 && warp < 14) kap_r = kappa[(size_t)b * KK + (warp - 4)];
    const int len32_r = lens32[b];        // candidate if dtype == int32
    const int len64_r = lens32[2 * b];    // candidate if dtype == int64 (low word)

    // ---- dtype probe: int64 layout <=> all odd int32 words in [0,256) are zero ----
    if (tid < 128) {
        int v = lens32[2 * tid + 1];
        #pragma unroll
        for (int o = 16; o; o >>= 1) v |= __shfl_xor_sync(0xffffffffu, v, o);
        if (lane == 0) or_sh[s][warp] = v;
    }

    // ---- PHASE 1: lin = x[b] @ W^T + bias, 2 dots/warp, then lane0 directly
    //      computes & stores its own alpha/beta/new_kappa (no warp-0 phase) ----
    {
        const float4* xs = (const float4*)(x + (size_t)b * HH);
        const int j0 = warp;
        const int j1 = warp + 16;
        const bool h1 = (j1 < 3 * KK);                 // warps 14,15 have no j1
        const float4* W0 = (const float4*)(W + (size_t)j0 * HH);
        const float4* W1 = (const float4*)(W + (size_t)(h1 ? j1 : j0) * HH);
        float s0 = 0.f, s1 = 0.f, s2 = 0.f, s3 = 0.f;
        float t0 = 0.f, t1 = 0.f, t2 = 0.f, t3 = 0.f;
        #pragma unroll
        for (int i = 0; i < HH / 4 / 32; i++) {        // 8 iterations, MLP ~24
            float4 xv = xs[i * 32 + lane];
            float4 w0 = W0[i * 32 + lane];
            float4 w1 = W1[i * 32 + lane];
            s0 = fmaf(xv.x, w0.x, s0);  t0 = fmaf(xv.x, w1.x, t0);
            s1 = fmaf(xv.y, w0.y, s1);  t1 = fmaf(xv.y, w1.y, t1);
            s2 = fmaf(xv.z, w0.z, s2);  t2 = fmaf(xv.z, w1.z, t2);
            s3 = fmaf(xv.w, w0.w, s3);  t3 = fmaf(xv.w, w1.w, t3);
        }
        float sv = (s0 + s1) + (s2 + s3);
        float tv = (t0 + t1) + (t2 + t3);
        #pragma unroll
        for (int o = 16; o; o >>= 1) {
            sv += __shfl_xor_sync(0xffffffffu, sv, o);
            tv += __shfl_xor_sync(0xffffffffu, tv, o);
        }
        if (lane == 0) {
            float va = sv + bias[j0];
            if (j0 < KK)            alpha_sh[s][j0]      = __expf(va);
            else                    beta_sh[s][j0 - KK]  = __expf(va);   // j0 in 10..15
            if (h1) {
                float vb = tv + bias[j1];
                if (j1 < 2 * KK) {
                    beta_sh[s][j1 - KK] = __expf(vb);                    // j1 in 16..19
                } else {
                    float nk = kap_r + __expf(vb - 3.9f);                // j1 in 20..29
                    nk_sh[s][j1 - 2 * KK] = nk;
                    out[(size_t)BB * VV + (size_t)b * KK + (j1 - 2 * KK)] = nk;
                }
            }
        }
    }

    // ---- PHASE 2 (fire-and-forget): prefetch first UCAP rows of c[b] (15 KB) ----
    {
        const float4* src = (const float4*)(c + (size_t)b * UU * VV);
        float4*       dst = (float4*)c_sh[s];
        for (int i = tid; i < UCAP * VV / 4; i += HT)
            __pipeline_memcpy_async(&dst[i], &src[i], 16);
        __pipeline_commit();
    }

    // ---- PHASE 3 (fire-and-forget stores): zeros for phi_termination[ZSTART..UU].
    //      phi overwrites [ZSTART, ucut] later if needed; named barriers order it. ----
    {
        int start = ZSTART;
        int mis = (int)((16u - ((uint32_t)(uintptr_t)(phit + start) & 15u)) & 15u) >> 2;
        if (tid < mis) phit[start + tid] = 0.f;
        start += mis;
        const int nv = (UU + 1 - start) >> 2;
        float4* p4 = (float4*)(phit + start);
        const float4 z = make_float4(0.f, 0.f, 0.f, 0.f);
        for (int i = tid; i < nv; i += HT) p4[i] = z;
        const int rem = start + nv * 4;
        if (tid < (UU + 1 - rem)) phit[rem + tid] = 0.f;
    }
    HSYNC();   // barrier 1: params + zeros + probe visible

    // ---- every warp redundantly computes the cutoff (no extra barrier):
    //      beyond nk + sqrt(105/beta), fp32 exp arg < -105 => exp == 0 exactly ----
    int ucut;
    {
        float cut = 0.f;
        if (lane < KK)
            cut = nk_sh[s][lane] + sqrtf(105.0f / beta_sh[s][lane]);
        #pragma unroll
        for (int o = 16; o; o >>= 1)
            cut = fmaxf(cut, __shfl_xor_sync(0xffffffffu, cut, o));
        int uc = (int)cut + 1;
        if (uc > UU) uc = UU;       // cap: correctness never depends on the cutoff
        if (uc < 0)  uc = 0;
        ucut = uc;
    }

    // ---- len / umax (off the post-phi path; or_sh valid after barrier 1) ----
    const int orv = or_sh[s][0] | or_sh[s][1] | or_sh[s][2] | or_sh[s][3];
    const int len = (orv == 0) ? len64_r : len32_r;
    int umax = ucut + 1;
    if (len < umax) umax = len;
    if (umax < 0)   umax = 0;
    if (umax > UU)  umax = UU;

    // ---- phi phase covers [0, max(ucut, ZSTART-1)]: computed vals for u <= ucut,
    //      literal zeros for (ucut, ZSTART) ----
    {
        const int utop = (ucut > ZSTART - 1) ? ucut : (ZSTART - 1);
        if (tid <= utop) {
            float a_r[KK], be_r[KK], nk_r[KK];
            #pragma unroll
            for (int k = 0; k < KK; k++) {
                a_r[k] = alpha_sh[s][k]; be_r[k] = beta_sh[s][k]; nk_r[k] = nk_sh[s][k];
            }
            for (int u = tid; u <= utop; u += HT) {
                float val = 0.f;
                if (u <= ucut) {
                    const float uf = (float)u;
                    #pragma unroll
                    for (int k = 0; k < KK; k++) {
                        float d   = nk_r[k] - uf;
                        float arg = -be_r[k] * d * d;
                        val += a_r[k] * __expf(arg);   // fast exp: ~1e-6 rel, << 1e-3
                    }
                }
                phit[u] = val;
                if (u < UCAP) phi_sh[s][u] = val;
            }
        }
    }
    __pipeline_wait_prior(0);   // c prefetch done (latency long since hidden)
    HSYNC();   // barrier 2: phi visible — LAST barrier; warps 10..15 exit after

    // ---- einsum: w[b,v] = sum_u phi[u]*c[b,u,v]; t = v*4+g over 320 threads.
    //      The 4 u-group partials for each v sit in adjacent lanes of one warp:
    //      reduce with 2 shfl_xor, lane g==0 stores. No barrier, no smem. ----
    if (tid < NGRP * VV) {               // 320 = 10 full warps
        const int v = tid >> 2;
        const int g = tid & 3;
        float acc = 0.f;
        const int ufast = umax < UCAP ? umax : UCAP;
        for (int u = g; u < ufast; u += NGRP)
            acc = fmaf(phi_sh[s][u], c_sh[s][u * VV + v], acc);
        if (umax > UCAP) {
            // rare fallback: gmem c + recomputed phi
            const float* cb = c + (size_t)b * UU * VV + v;
            for (int u = UCAP + g; u < umax; u += NGRP) {
                const float uf = (float)u;
                float ph = 0.f;
                #pragma unroll
                for (int k = 0; k < KK; k++) {
                    float d = nk_sh[s][k] - uf;
                    ph += alpha_sh[s][k] * __expf(-beta_sh[s][k] * d * d);
                }
                acc = fmaf(ph, cb[(size_t)u * VV], acc);
            }
        }
        acc += __shfl_xor_sync(0xffffffffu, acc, 1);
        acc += __shfl_xor_sync(0xffffffffu, acc, 2);
        if (g == 0) out[(size_t)b * VV + v] = acc;
    }
}

extern "C" void kernel_launch(void* const* d_in, const int* in_sizes, int n_in,
                              void* d_out, int out_size) {
    const float* x     = (const float*)d_in[0];
    const float* c     = (const float*)d_in[1];
    const float* kappa = (const float*)d_in[2];
    const float* W     = (const float*)d_in[3];
    const float* bias  = (const float*)d_in[4];
    const int*   lens  = (const int*)d_in[5];
    float* out = (float*)d_out;

    softwindow_kernel<<<BB / 2, NT>>>(x, c, kappa, W, bias, lens, out);
}